// round 14
// baseline (speedup 1.0000x reference)
#include <cuda_runtime.h>
#include <cuda_fp16.h>
#include <cstdint>

// Correlation cost volume via single-pass fp16 tensor MMA (fp32 accumulate).
//   out[b,i,h,x] = (1/128) * sum_c L[b,c,h,x] * R[b,c,h,x-i],  x>=i, else 0
// b=8, c=128, h=96, w=320, D=48.
//
// R14: persistent CTAs (grid = 2*SMs) with the R12 staging invariant kept
// intact: within one iteration, loads(c) ... domma ... stage(c) operate on
// the SAME chunk c (R13 broke this and staged the wrong chunk). At k==3 the
// CTA switches context and issues next tile's chunk-0 LDGs; they fly through
// the epilogue and are staged stall-free at the next loop top. Cold-load
// prologue paid once per CTA. L2 prefetch runs ahead across tile boundaries.

namespace {
constexpr int kB = 8, kC = 128, kH = 96, kW = 320, kD = 48;
constexpr int CHW = kH * kW;            // 30720
constexpr int TM = 160;                 // x per tile
constexpr int TN = TM + kD;             // 208 x' rows staged
constexpr int NT = 320;                 // 10 warps; warp wid owns m16 tile
constexpr int NCHUNK = 4;               // 32 channels per chunk
constexpr int NTILES = 2 * kB * kH;     // 1536

// row = 64 B (32 fp16) per chunk
constexpr int OFF_A = 0;                // 160*64 = 10240
constexpr int OFF_B = TM * 64;          // B: 208*64 = 13312
constexpr int BUFB  = OFF_B + TN * 64;  // 23552
constexpr int OFF_BNC = 2 * BUFB;       // 47104 (separate from staging)
constexpr int BNC_PITCH = 81;           // floats per bounce row
constexpr int SMEM_TOTAL = OFF_BNC + TM * BNC_PITCH * 4;   // 98944
}

__device__ __forceinline__ uint32_t smem_u32(const void* p) {
    uint32_t a;
    asm("{ .reg .u64 t; cvta.to.shared.u64 t, %1; cvt.u32.u64 %0, t; }" : "=r"(a) : "l"(p));
    return a;
}
__device__ __forceinline__ void ldsm_x4(uint32_t* r, uint32_t addr) {
    asm volatile("ldmatrix.sync.aligned.m8n8.x4.shared.b16 {%0,%1,%2,%3}, [%4];"
                 : "=r"(r[0]), "=r"(r[1]), "=r"(r[2]), "=r"(r[3]) : "r"(addr));
}
__device__ __forceinline__ void mma_f16(float* d, const uint32_t* a, const uint32_t* b) {
    asm volatile(
        "mma.sync.aligned.m16n8k16.row.col.f32.f16.f16.f32 "
        "{%0,%1,%2,%3}, {%4,%5,%6,%7}, {%8,%9}, {%0,%1,%2,%3};"
        : "+f"(d[0]), "+f"(d[1]), "+f"(d[2]), "+f"(d[3])
        : "r"(a[0]), "r"(a[1]), "r"(a[2]), "r"(a[3]), "r"(b[0]), "r"(b[1]));
}
__device__ __forceinline__ void pf_l2(const char* p) {
    asm volatile("prefetch.global.L2 [%0];" :: "l"(p));
}

// pitch-64 swizzle: 16B line ^= (row>>1)&3 (CF for STS.128 and ldmatrix).
__device__ __forceinline__ uint32_t swoff(uint32_t row, uint32_t line) {
    return row * 64u + ((line ^ ((row >> 1) & 3u)) << 4);
}

extern __shared__ char smem[];

__global__ __launch_bounds__(NT, 2)
void costvol_persist2(const float* __restrict__ L, const float* __restrict__ R,
                      float* __restrict__ out) {
    const uint32_t sb = smem_u32(smem);
    const int tid = threadIdx.x;
    const int wid = tid >> 5;
    const int lid = tid & 31;
    const int G = gridDim.x;

    // ---- tile-independent staging geometry (per thread) ----
    const int g8A   = tid / TM;              // 0/1 (slot1 adds +2)
    const int rowAs = tid - g8A * TM;
    const int g8B0 = tid / TN;
    const int rowB0 = tid - g8B0 * TN;
    const int g8B1 = (tid + NT) / TN;
    const int rowB1 = tid + NT - g8B1 * TN;
    const int rowB2 = tid + 16;              // g8 = 3, valid if tid<192

    // ---- tile-independent prefetch slots (448 = 32ch x (6 A + 8 B lines)) ----
    const int cc0 = tid / 14,             li0 = tid % 14;
    const int s1  = tid + NT;
    const bool pf1v = (s1 < 448);
    const int cc1 = (pf1v ? s1 : 0) / 14, li1 = (pf1v ? s1 : 0) % 14;
    const char* const pfEndL = (const char*)(L + (long)kB * kC * CHW) - 128;
    const char* const pfEndR = (const char*)(R + (long)kB * kC * CHW) - 128;

    // ---- load context (tile-dependent, switched at k==3) ----
    const float *pA0, *pA1, *pB0b, *pB1b, *pB2b;
    bool okB0, okB1, okB2;

    auto set_ctx = [&](int u) {
        const int Xu = (u & 1) * TM;
        const int bhu = u >> 1;
        const int bu = bhu / kH;
        const int hu = bhu - bu * kH;
        const float* Lb = L + ((long)(bu * kC) * kH + hu) * kW;
        const float* Rb = R + ((long)(bu * kC) * kH + hu) * kW;
        const int xp0 = Xu - kD + rowB0;
        const int xp1 = Xu - kD + rowB1;
        const int xp2 = Xu - kD + rowB2;
        okB0 = (xp0 >= 0);
        okB1 = (xp1 >= 0);
        okB2 = (tid < 192) && (xp2 >= 0);
        pA0  = Lb + (long)(8 * g8A) * CHW + Xu + rowAs;
        pA1  = pA0 + (long)16 * CHW;
        pB0b = Rb + (long)(8 * g8B0) * CHW + (okB0 ? xp0 : 0);
        pB1b = Rb + (long)(8 * g8B1) * CHW + (okB1 ? xp1 : 0);
        pB2b = Rb + (long)(8 * 3)    * CHW + (okB2 ? xp2 : 0);
    };

    auto prefetch = [&](int u, int c) {   // prefetch chunk c of tile u
        if (u >= NTILES) return;
        const int Xu = (u & 1) * TM;
        const int bhu = u >> 1;
        const int bu = bhu / kH;
        const int hu = bhu - bu * kH;
        const int xr = (Xu - kD) > 0 ? (Xu - kD) : 0;
        {
            const int cc = cc0 + 32 * c;
            const float* p = (li0 < 6)
                ? (L + ((long)(bu * kC + cc) * kH + hu) * kW + Xu)
                : (R + ((long)(bu * kC + cc) * kH + hu) * kW + xr);
            const char* a = (const char*)((uintptr_t)p & ~(uintptr_t)127)
                          + (long)(li0 < 6 ? li0 : li0 - 6) * 128;
            const char* e = (li0 < 6) ? pfEndL : pfEndR;
            pf_l2(a < e ? a : e);
        }
        if (pf1v) {
            const int cc = cc1 + 32 * c;
            const float* p = (li1 < 6)
                ? (L + ((long)(bu * kC + cc) * kH + hu) * kW + Xu)
                : (R + ((long)(bu * kC + cc) * kH + hu) * kW + xr);
            const char* a = (const char*)((uintptr_t)p & ~(uintptr_t)127)
                          + (long)(li1 < 6 ? li1 : li1 - 6) * 128;
            const char* e = (li1 < 6) ? pfEndL : pfEndR;
            pf_l2(a < e ? a : e);
        }
    };

    float fA0[8], fA1[8], fB0[8], fB1[8], fB2[8];

    auto loads = [&](int c) {
        const long co = (long)(32 * c) * CHW;
#pragma unroll
        for (int j = 0; j < 8; j++) {
            fA0[j] = pA0[co + j * CHW];
            fA1[j] = pA1[co + j * CHW];
            fB0[j] = okB0 ? pB0b[co + j * CHW] : 0.f;
            fB1[j] = okB1 ? pB1b[co + j * CHW] : 0.f;
            fB2[j] = okB2 ? pB2b[co + j * CHW] : 0.f;
        }
    };

    auto cvt_store = [&](const float* f, int base_off, int row, int g8) {
        __half2 p0 = __floats2half2_rn(f[0], f[1]);
        __half2 p1 = __floats2half2_rn(f[2], f[3]);
        __half2 p2 = __floats2half2_rn(f[4], f[5]);
        __half2 p3 = __floats2half2_rn(f[6], f[7]);
        uint4 v;
        v.x = *reinterpret_cast<uint32_t*>(&p0);
        v.y = *reinterpret_cast<uint32_t*>(&p1);
        v.z = *reinterpret_cast<uint32_t*>(&p2);
        v.w = *reinterpret_cast<uint32_t*>(&p3);
        *reinterpret_cast<uint4*>(smem + base_off + swoff((uint32_t)row, (uint32_t)g8)) = v;
    };

    auto stage = [&](int buf) {
        const int bo = buf * BUFB;
        cvt_store(fA0, bo + OFF_A, rowAs, g8A);
        cvt_store(fA1, bo + OFF_A, rowAs, g8A + 2);
        cvt_store(fB0, bo + OFF_B, rowB0, g8B0);
        cvt_store(fB1, bo + OFF_B, rowB1, g8B1);
        if (tid < 192) cvt_store(fB2, bo + OFF_B, rowB2, 3);
    };

    // ---- consumer: warp wid owns m rows [16wid,16wid+16), 64-row B window
    float acc[8][4];
#pragma unroll
    for (int j = 0; j < 8; j++)
#pragma unroll
        for (int q = 0; q < 4; q++) acc[j][q] = 0.f;

    const uint32_t rowA = 16u * wid + (lid & 15);
    const uint32_t aHalf = (uint32_t)(lid >> 4);
    const uint32_t bRow  = 8u * (uint32_t)(lid >> 4) + (lid & 7);
    const uint32_t bHalf = (uint32_t)((lid >> 3) & 1);

    auto domma = [&](int buf) {
        const uint32_t base = sb + buf * BUFB;
#pragma unroll
        for (int ks = 0; ks < 2; ks++) {
            uint32_t a4[4];
            ldsm_x4(a4, base + OFF_A + swoff(rowA, 2u * ks + aHalf));
#pragma unroll
            for (int jp = 0; jp < 4; jp++) {
                uint32_t b4[4];
                ldsm_x4(b4, base + OFF_B
                            + swoff(16u * wid + 16u * jp + bRow, 2u * ks + bHalf));
                mma_f16(acc[2 * jp],     a4, b4);
                mma_f16(acc[2 * jp + 1], a4, b4 + 2);
            }
        }
    };

    // ---- persistent tile loop ----
    int t = blockIdx.x;
    if (t >= NTILES) return;
    set_ctx(t);
    prefetch(t, 1);
    prefetch(t, 2);
    loads(0);                       // cold stall: once per CTA

#pragma unroll 1
    for (; t < NTILES; t += G) {
        const int tn = t + G;       // next tile for this CTA
        // epilogue coords of THIS tile (ctx switches to tn at k==3)
        const int Xt = (t & 1) * TM;
        const int bht = t >> 1;
        const int bt = bht / kH;
        const int ht = bht - bt * kH;

        // f regs hold chunk0 of tile t (loaded at prior k==3 or prologue)
        stage(0);                   // regs are old -> no scoreboard stall
        __syncthreads();

        // R12 invariant: loads(c) ... domma ... stage(c) in the SAME iteration
#pragma unroll
        for (int k = 0; k < NCHUNK; k++) {
            if (k == 0)      prefetch(t, 3);
            else if (k == 1) prefetch(tn, 0);
            else if (k == 2) prefetch(tn, 1);
            else             prefetch(tn, 2);
            if (k < 3) {
                loads(k + 1);
                domma(k & 1);
                stage((k + 1) & 1);
            } else {
                if (tn < NTILES) { set_ctx(tn); loads(0); }  // flies thru epilogue
                domma(k & 1);
            }
            __syncthreads();
        }

        // ---- epilogue: acc -> bounce (scaled) + reset; then coalesced STG ----
        {
            float* bnc = reinterpret_cast<float*>(smem + OFF_BNC);
            const float sc = 1.0f / (float)kC;
            const int q = lid >> 2;
            const int e = lid & 3;
            const int m0 = 16 * wid + q;
#pragma unroll
            for (int j = 0; j < 8; j++) {
                const int col = 8 * j + 2 * e;
                bnc[m0 * BNC_PITCH + col]           = acc[j][0] * sc;
                bnc[m0 * BNC_PITCH + col + 1]       = acc[j][1] * sc;
                bnc[(m0 + 8) * BNC_PITCH + col]     = acc[j][2] * sc;
                bnc[(m0 + 8) * BNC_PITCH + col + 1] = acc[j][3] * sc;
#pragma unroll
                for (int q2 = 0; q2 < 4; q2++) acc[j][q2] = 0.f;
            }
        }
        __syncthreads();
        {
            const int half = tid / TM;               // 0 or 1
            const int xl   = tid - half * TM;        // 0..159
            const float* bnr = reinterpret_cast<const float*>(smem + OFF_BNC)
                             + xl * BNC_PITCH + (xl & 15) + 48;
            float* ob = out + (long)(bt * kD) * CHW + ht * kW + Xt + xl;
#pragma unroll
            for (int it = 0; it < 24; it++) {
                const int i = 2 * it + half;
                ob[(long)i * CHW] = bnr[-i];
            }
        }
        // bounce region is disjoint from staging; next loop-top stage(0)
        // can overlap stragglers of this STG loop safely.
    }
}

extern "C" void kernel_launch(void* const* d_in, const int* in_sizes, int n_in,
                              void* d_out, int out_size) {
    const float* L = (const float*)d_in[0];
    const float* R = (const float*)d_in[1];
    float* out = (float*)d_out;

    cudaFuncSetAttribute(costvol_persist2,
                         cudaFuncAttributeMaxDynamicSharedMemorySize, SMEM_TOTAL);

    int nsm = 148;
    cudaDeviceGetAttribute(&nsm, cudaDevAttrMultiProcessorCount, 0);
    const int grid = 2 * nsm;               // persistent: one resident wave
    costvol_persist2<<<grid, NT, SMEM_TOTAL>>>(L, R, out);
}

// round 16
// speedup vs baseline: 1.5755x; 1.5755x over previous
#include <cuda_runtime.h>
#include <cuda_fp16.h>
#include <cstdint>

// Correlation cost volume via single-pass fp16 tensor MMA (fp32 accumulate).
//   out[b,i,h,x] = (1/128) * sum_c L[b,c,h,x] * R[b,c,h,x-i],  x>=i, else 0
// b=8, c=128, h=96, w=320, D=48.
//
// R16 = R15 with the A-fragment ldmatrix ordering FIXED. mma A fragment
// matrix order is a0=(m0-7,k0-7), a1=(m8-15,k0-7), a2=(m0-7,k8-15),
// a3=(m8-15,k8-15): group bit0 = m-half, bit1 = k-half. (B differs:
// bit0 = k-half, bit1 = n-half — R15 had B right and A swapped.)
// Staging is x-contiguous ([ch][x]) -> LDG.128 (10/thread/chunk, was 40
// scalar LDG.32 in R12 = the LSU-issue bottleneck) + contiguous STS.64;
// consumer uses ldmatrix.x4.trans. Pitches 336B/432B -> conflict-free.

namespace {
constexpr int kB = 8, kC = 128, kH = 96, kW = 320, kD = 48;
constexpr int CHW = kH * kW;            // 30720
constexpr int TM = 160;                 // x per CTA tile
constexpr int TN = TM + kD;             // 208 x' cols staged
constexpr int NT = 320;                 // 10 warps; warp wid owns m16 tile
constexpr int NCHUNK = 4;               // 32 channels per chunk

constexpr int A_PITCH = 336;            // bytes per ch row (160 fp16 + pad)
constexpr int B_PITCH = 432;            // bytes per ch row (208 fp16 + pad)
constexpr int OFF_A = 0;                // A: 32 ch rows
constexpr int OFF_B = 32 * A_PITCH;     // 10752; B: 32 ch rows = 13824
constexpr int BUFB  = OFF_B + 32 * B_PITCH;   // 24576
constexpr int BNC_PITCH = 81;           // floats per bounce row
constexpr int SMEM_TOTAL = TM * BNC_PITCH * 4;   // 51840 > 2*BUFB (49152)
}

__device__ __forceinline__ uint32_t smem_u32(const void* p) {
    uint32_t a;
    asm("{ .reg .u64 t; cvta.to.shared.u64 t, %1; cvt.u32.u64 %0, t; }" : "=r"(a) : "l"(p));
    return a;
}
__device__ __forceinline__ void ldsm_x4_t(uint32_t* r, uint32_t addr) {
    asm volatile("ldmatrix.sync.aligned.m8n8.x4.trans.shared.b16 {%0,%1,%2,%3}, [%4];"
                 : "=r"(r[0]), "=r"(r[1]), "=r"(r[2]), "=r"(r[3]) : "r"(addr));
}
__device__ __forceinline__ void mma_f16(float* d, const uint32_t* a, const uint32_t* b) {
    asm volatile(
        "mma.sync.aligned.m16n8k16.row.col.f32.f16.f16.f32 "
        "{%0,%1,%2,%3}, {%4,%5,%6,%7}, {%8,%9}, {%0,%1,%2,%3};"
        : "+f"(d[0]), "+f"(d[1]), "+f"(d[2]), "+f"(d[3])
        : "r"(a[0]), "r"(a[1]), "r"(a[2]), "r"(a[3]), "r"(b[0]), "r"(b[1]));
}
__device__ __forceinline__ void pf_l2(const char* p) {
    asm volatile("prefetch.global.L2 [%0];" :: "l"(p));
}

extern __shared__ char smem[];

__global__ __launch_bounds__(NT, 2)
void costvol_ldsmT2(const float* __restrict__ L, const float* __restrict__ R,
                    float* __restrict__ out) {
    const uint32_t sb = smem_u32(smem);
    const int tid = threadIdx.x;
    const int wid = tid >> 5;
    const int lid = tid & 31;

    const int tile = blockIdx.x;            // 0..1
    const int bh   = blockIdx.y;            // 0..767
    const int b = bh / kH;
    const int h = bh - b * kH;
    const int X = tile * TM;

    const float* Lb = L + ((long)(b * kC) * kH + h) * kW;
    const float* Rb = R + ((long)(b * kC) * kH + h) * kW;

    // ---- staging slots: quads of 4 consecutive x for one channel ----
    // A: 32ch x 40 quads = 1280 slots; thread t owns (chA0+8i, xqA), i=0..3
    const int chA0 = tid / 40;
    const int xqA  = tid - chA0 * 40;
    const float* pA = Lb + (long)chA0 * CHW + X + xqA * 4;
    const uint32_t stA = (uint32_t)(OFF_A + chA0 * A_PITCH + xqA * 8);

    // B: 32ch x 52 quads = 1664 slots; thread t owns slots t+320*i, i=0..5
    int   offB[6];        // float offset into Rb; -1 => zero quad / no slot
    uint32_t stB[6];
#pragma unroll
    for (int i = 0; i < 6; i++) {
        const int s = tid + 320 * i;
        if (s < 1664) {
            const int ch = s / 52;
            const int xq = s - ch * 52;
            const int xp = X - kD + xq * 4;
            offB[i] = (xp >= 0) ? (ch * CHW + xp) : -1;
            stB[i]  = (uint32_t)(OFF_B + ch * B_PITCH + xq * 8);
        } else {
            offB[i] = -1;
            stB[i]  = 0xFFFFFFFFu;   // marker: no slot
        }
    }

    // ---- L2 prefetch slots: per ch, A 5 lines + B 7 lines = 12; 384 total ----
    const int cc0 = tid / 12, li0 = tid % 12;
    const bool pf1v = (tid < 64);
    const int s1 = tid + 320;
    const int cc1 = s1 / 12, li1 = s1 % 12;
    const int xr = (X - kD) > 0 ? (X - kD) : 0;
    const char* const pfEndL = (const char*)(L + (long)kB * kC * CHW) - 128;
    const char* const pfEndR = (const char*)(R + (long)kB * kC * CHW) - 128;

    auto prefetch = [&](int c) {
        {
            const int cc = cc0 + 32 * c;
            const char* a;
            const char* e;
            if (li0 < 5) { a = (const char*)(Lb + (long)cc * CHW + X) + li0 * 128; e = pfEndL; }
            else {
                const float* p = Rb + (long)cc * CHW + xr;
                a = (const char*)((uintptr_t)p & ~(uintptr_t)127) + (li0 - 5) * 128;
                e = pfEndR;
            }
            pf_l2(a < e ? a : e);
        }
        if (pf1v) {
            const int cc = cc1 + 32 * c;
            const char* a;
            const char* e;
            if (li1 < 5) { a = (const char*)(Lb + (long)cc * CHW + X) + li1 * 128; e = pfEndL; }
            else {
                const float* p = Rb + (long)cc * CHW + xr;
                a = (const char*)((uintptr_t)p & ~(uintptr_t)127) + (li1 - 5) * 128;
                e = pfEndR;
            }
            pf_l2(a < e ? a : e);
        }
    };

    // ---- register prefetch: one chunk of quads ----
    float4 qA[4], qB[6];

    auto loads = [&](int c) {
        const int co = c * 32 * CHW;
#pragma unroll
        for (int i = 0; i < 4; i++)
            qA[i] = *reinterpret_cast<const float4*>(pA + co + i * 8 * CHW);
#pragma unroll
        for (int i = 0; i < 6; i++) {
            if (offB[i] >= 0)
                qB[i] = *reinterpret_cast<const float4*>(Rb + (long)offB[i] + co);
            else
                qB[i] = make_float4(0.f, 0.f, 0.f, 0.f);
        }
    };

    auto stage = [&](int buf) {
        const int bo = buf * BUFB;
#pragma unroll
        for (int i = 0; i < 4; i++) {
            __half2 h0 = __floats2half2_rn(qA[i].x, qA[i].y);
            __half2 h1 = __floats2half2_rn(qA[i].z, qA[i].w);
            uint2 v;
            v.x = *reinterpret_cast<uint32_t*>(&h0);
            v.y = *reinterpret_cast<uint32_t*>(&h1);
            *reinterpret_cast<uint2*>(smem + bo + stA + i * 8 * A_PITCH) = v;
        }
#pragma unroll
        for (int i = 0; i < 6; i++) {
            if (stB[i] != 0xFFFFFFFFu) {
                __half2 h0 = __floats2half2_rn(qB[i].x, qB[i].y);
                __half2 h1 = __floats2half2_rn(qB[i].z, qB[i].w);
                uint2 v;
                v.x = *reinterpret_cast<uint32_t*>(&h0);
                v.y = *reinterpret_cast<uint32_t*>(&h1);
                *reinterpret_cast<uint2*>(smem + bo + stB[i]) = v;
            }
        }
    };

    // ---- consumer: warp wid owns m rows [16wid,16wid+16), B window 64 cols
    float acc[8][4];
#pragma unroll
    for (int j = 0; j < 8; j++)
#pragma unroll
        for (int q = 0; q < 4; q++) acc[j][q] = 0.f;

    // ldmatrix.trans lane addressing. group = lid>>3 (matrix index).
    // A fragment order: bit0 = m-half, bit1 = k-half.
    // B fragment order: bit0 = k-half, bit1 = n-half.
    const uint32_t r8 = (uint32_t)(lid & 7);
    const uint32_t bit0 = (uint32_t)((lid >> 3) & 1);
    const uint32_t bit1 = (uint32_t)((lid >> 4) & 1);
    const uint32_t aLane = (bit1 * 8 + r8) * A_PITCH          // k row (bit1)
                         + (16u * wid + bit0 * 8) * 2 + OFF_A; // m col (bit0)
    const uint32_t bLane = (bit0 * 8 + r8) * B_PITCH          // k row (bit0)
                         + (16u * wid + bit1 * 8) * 2 + OFF_B; // n col (bit1)

    auto domma = [&](int buf) {
        const uint32_t base = sb + (uint32_t)(buf * BUFB);
#pragma unroll
        for (int ks = 0; ks < 2; ks++) {
            uint32_t a4[4];
            ldsm_x4_t(a4, base + aLane + (uint32_t)(ks * 16 * A_PITCH));
#pragma unroll
            for (int jp = 0; jp < 4; jp++) {
                uint32_t b4[4];
                ldsm_x4_t(b4, base + bLane
                              + (uint32_t)(ks * 16 * B_PITCH) + (uint32_t)(jp * 32));
                mma_f16(acc[2 * jp],     a4, b4);
                mma_f16(acc[2 * jp + 1], a4, b4 + 2);
            }
        }
    };

    // ---- pipeline (R12 schedule): pf(k+2); loads(k+1); domma(k); stage(k+1) ----
    prefetch(0);
    prefetch(1);
    loads(0);
    stage(0);
    __syncthreads();
#pragma unroll
    for (int k = 0; k < NCHUNK; k++) {
        if (k + 2 < NCHUNK) prefetch(k + 2);
        if (k + 1 < NCHUNK) loads(k + 1);
        domma(k & 1);
        if (k + 1 < NCHUNK) stage((k + 1) & 1);
        __syncthreads();
    }

    // ---- acc -> bounce (scaled): warp wid rows [16wid,16wid+16), 64 cols ----
    {
        float* bnc = reinterpret_cast<float*>(smem);
        const float sc = 1.0f / (float)kC;
        const int q = lid >> 2;
        const int e = lid & 3;
        const int m0 = 16 * wid + q;
#pragma unroll
        for (int j = 0; j < 8; j++) {
            const int col = 8 * j + 2 * e;
            bnc[m0 * BNC_PITCH + col]           = acc[j][0] * sc;
            bnc[m0 * BNC_PITCH + col + 1]       = acc[j][1] * sc;
            bnc[(m0 + 8) * BNC_PITCH + col]     = acc[j][2] * sc;
            bnc[(m0 + 8) * BNC_PITCH + col + 1] = acc[j][3] * sc;
        }
    }
    __syncthreads();

    // ---- out[b,i,h,X+xl] = bounce[xl][(xl&15) + 48 - i], coalesced in x ----
    {
        const int half = tid / TM;               // 0 or 1
        const int xl   = tid - half * TM;        // 0..159
        const float* bnr = reinterpret_cast<const float*>(smem)
                         + xl * BNC_PITCH + (xl & 15) + 48;
        float* ob = out + (long)(b * kD) * CHW + h * kW + X + xl;
#pragma unroll
        for (int it = 0; it < 24; it++) {
            const int i = 2 * it + half;
            ob[(long)i * CHW] = bnr[-i];
        }
    }
}

extern "C" void kernel_launch(void* const* d_in, const int* in_sizes, int n_in,
                              void* d_out, int out_size) {
    const float* L = (const float*)d_in[0];
    const float* R = (const float*)d_in[1];
    float* out = (float*)d_out;

    cudaFuncSetAttribute(costvol_ldsmT2,
                         cudaFuncAttributeMaxDynamicSharedMemorySize, SMEM_TOTAL);

    dim3 grid(kW / TM, kB * kH);   // (2, 768) = 1536 CTAs
    costvol_ldsmT2<<<grid, NT, SMEM_TOTAL>>>(L, R, out);
}